// round 8
// baseline (speedup 1.0000x reference)
#include <cuda_runtime.h>
#include <cuda_fp16.h>
#include <cstdint>

#define SLEN 2048
#define BSZ  2
#define EMB  1024
#define NH   16
#define DHD  64
#define PFW  16
#define MTOK (SLEN*BSZ)
#define GBK  64              // K per chunk (halves)
#define NCHUNK (EMB/GBK)     // 16
#define GBM  128
#define GBN  256
#define STAGES 4
#define ROWB 144             // padded smem row bytes (128 data + 16 pad)
#define STGB ((GBM+GBN)*ROWB)    // 55296
#define GEMM_SMEM (STAGES*STGB)  // 221184
#define GTHR 512
#define NQKV 3072

// ---------------- scratch (static device arrays; no allocation) -------------
__device__ __align__(16) __half g_xn [MTOK*EMB];        // LN out fp16
__device__ __align__(16) __half g_att[MTOK*EMB];        // attn out fp16
__device__ __align__(16) __half g_wh [4*EMB*EMB];       // Wq|Wk|Wv|Wo fp16, [N][K]
__device__ __align__(16) __half g_qkv[MTOK*NQKV];       // fused QKV output (fp16)
__device__ float g_bias[NQKV];

// ---------------- PTX helpers ------------------------------------------------
__device__ __forceinline__ uint32_t s2u(const void* p) {
    uint32_t a;
    asm("{ .reg .u64 t; cvta.to.shared.u64 t, %1; cvt.u32.u64 %0, t; }" : "=r"(a) : "l"(p));
    return a;
}
__device__ __forceinline__ void cp16(uint32_t dst, const void* src) {
    asm volatile("cp.async.cg.shared.global [%0], [%1], 16;" :: "r"(dst), "l"(src));
}
#define CP_COMMIT() asm volatile("cp.async.commit_group;" ::: "memory")

__device__ __forceinline__ void ldsm4(uint32_t* r, uint32_t addr) {
    asm volatile("ldmatrix.sync.aligned.m8n8.x4.shared.b16 {%0,%1,%2,%3}, [%4];"
        : "=r"(r[0]), "=r"(r[1]), "=r"(r[2]), "=r"(r[3]) : "r"(addr));
}
__device__ __forceinline__ void mma16816(float* d, const uint32_t* a,
                                         uint32_t b0, uint32_t b1) {
    asm volatile("mma.sync.aligned.m16n8k16.row.col.f32.f16.f16.f32 "
        "{%0,%1,%2,%3}, {%4,%5,%6,%7}, {%8,%9}, {%0,%1,%2,%3};"
        : "+f"(d[0]), "+f"(d[1]), "+f"(d[2]), "+f"(d[3])
        : "r"(a[0]), "r"(a[1]), "r"(a[2]), "r"(a[3]), "r"(b0), "r"(b1));
}

// ---------------- weight prep: W[K,N] fp32 -> Wh[N,K] fp16 ------------------
__global__ void __launch_bounds__(256) wprep_kernel(
    const float* __restrict__ W0, const float* __restrict__ W1,
    const float* __restrict__ W2, const float* __restrict__ W3,
    __half* __restrict__ Bh)
{
    const float* W = (blockIdx.z == 0) ? W0 : (blockIdx.z == 1) ? W1
                   : (blockIdx.z == 2) ? W2 : W3;
    __half* B = Bh + (size_t)blockIdx.z * EMB * EMB;
    __shared__ float tile[32][33];
    int n0 = blockIdx.x * 32;
    int k0 = blockIdx.y * 32;
    int tx = threadIdx.x & 31;
    int ty = threadIdx.x >> 5;
    #pragma unroll
    for (int r = ty; r < 32; r += 8)
        tile[r][tx] = W[(size_t)(k0 + r) * EMB + n0 + tx];   // tile[k][n]
    __syncthreads();
    #pragma unroll
    for (int r = ty; r < 32; r += 8)
        B[(size_t)(n0 + r) * EMB + (k0 + tx)] = __float2half(tile[tx][r]);
}

__global__ void bias_cat_kernel(const float* __restrict__ bq,
                                const float* __restrict__ bk,
                                const float* __restrict__ bv,
                                float* __restrict__ bqkv)
{
    int i = blockIdx.x * 256 + threadIdx.x;
    if (i < NQKV)
        bqkv[i] = (i < EMB) ? bq[i] : (i < 2*EMB) ? bk[i - EMB] : bv[i - 2*EMB];
}

// ---------------- LayerNorm -> fp16 ----------------------------------------
__global__ void __launch_bounds__(256) ln_kernel(
    const float* __restrict__ x,
    const float* __restrict__ gamma,
    const float* __restrict__ beta,
    __half* __restrict__ xn)
{
    int row = blockIdx.x;
    int tid = threadIdx.x;
    const float4 xv = ((const float4*)(x + (size_t)row * EMB))[tid];
    float s  = xv.x + xv.y + xv.z + xv.w;
    float s2 = xv.x*xv.x + xv.y*xv.y + xv.z*xv.z + xv.w*xv.w;
    #pragma unroll
    for (int o = 16; o > 0; o >>= 1) {
        s  += __shfl_xor_sync(0xffffffffu, s,  o);
        s2 += __shfl_xor_sync(0xffffffffu, s2, o);
    }
    __shared__ float rs[8], rs2[8];
    __shared__ float mean_s, rstd_s;
    int w = tid >> 5, l = tid & 31;
    if (l == 0) { rs[w] = s; rs2[w] = s2; }
    __syncthreads();
    if (tid == 0) {
        float ts = 0.f, ts2 = 0.f;
        #pragma unroll
        for (int i = 0; i < 8; i++) { ts += rs[i]; ts2 += rs2[i]; }
        float mean = ts * (1.0f / EMB);
        float var  = ts2 * (1.0f / EMB) - mean * mean;
        mean_s = mean;
        rstd_s = rsqrtf(var + 1e-5f);
    }
    __syncthreads();
    float mean = mean_s, r = rstd_s;
    float4 gv = ((const float4*)gamma)[tid];
    float4 bv = ((const float4*)beta)[tid];
    __half h[4];
    h[0] = __float2half((xv.x - mean) * r * gv.x + bv.x);
    h[1] = __float2half((xv.y - mean) * r * gv.y + bv.y);
    h[2] = __float2half((xv.z - mean) * r * gv.z + bv.z);
    h[3] = __float2half((xv.w - mean) * r * gv.w + bv.w);
    *(uint2*)(xn + (size_t)row * EMB + tid * 4) = *(uint2*)h;
}

// ---------------- HMMA fp16 GEMM: C = A @ B^T + bias (+res) ----------------
// A: [M, 1024] fp16.  B: [N, 1024] fp16 ([N][K]).
// CTA tile 128x256, 16 warps (warp tile 32x64), GBK=64, 4-stage cp.async,
// fragment double-buffering across the 4 k-slices.
template<int OUT_HALF>
__global__ void __launch_bounds__(GTHR, 1) gemm_mma(
    const __half* __restrict__ A,
    const __half* __restrict__ B,
    const float* __restrict__ bias,
    const float* __restrict__ res,
    void* __restrict__ Cv,
    int ldc)
{
    extern __shared__ char smem[];
    uint32_t sb = s2u(smem);
    int tid = threadIdx.x;
    int w = tid >> 5, l = tid & 31;
    int bm = blockIdx.y * GBM;
    int bn = blockIdx.x * GBN;
    int wm = (w & 3) * 32;
    int wn = (w >> 2) * 64;

    // hoisted load addressing
    // A: 128 rows x 8 chunks -> thread: row=tid>>2, 2 chunks at (tid&3)*32 B
    // B: 256 rows x 8 chunks -> thread: row=tid>>1, 4 chunks at (tid&1)*64 B
    int ra = tid >> 2, ca = tid & 3;
    int rb = tid >> 1, cb = tid & 1;
    const __half* p0 = A + (size_t)(bm + ra) * EMB + ca * 16;
    const __half* p1 = B + (size_t)(bn + rb) * EMB + cb * 32;
    uint32_t d0 = (uint32_t)ra * ROWB + ca * 32;
    uint32_t d1 = (uint32_t)(GBM + rb) * ROWB + cb * 64;

    float acc[2][8][4];
    #pragma unroll
    for (int i = 0; i < 2; i++)
        #pragma unroll
        for (int j = 0; j < 8; j++)
            #pragma unroll
            for (int t = 0; t < 4; t++) acc[i][j][t] = 0.f;

    // prologue: fill STAGES-1 stages
    #pragma unroll
    for (int c = 0; c < STAGES - 1; c++) {
        uint32_t stg = sb + c * STGB;
        cp16(stg + d0, p0); cp16(stg + d0 + 16, p0 + 8); p0 += GBK;
        cp16(stg + d1, p1);      cp16(stg + d1 + 16, p1 + 8);
        cp16(stg + d1 + 32, p1 + 16); cp16(stg + d1 + 48, p1 + 24);
        p1 += GBK;
        CP_COMMIT();
    }

    uint32_t arow = (uint32_t)(wm + (l & 15)) * ROWB + ((l >> 4) << 4);
    uint32_t brow = (uint32_t)(GBM + wn + (l & 15)) * ROWB + ((l >> 4) << 4);

    for (int c0 = 0; c0 < NCHUNK; c0 += STAGES) {
        #pragma unroll
        for (int s = 0; s < STAGES; s++) {
            int c = c0 + s;
            asm volatile("cp.async.wait_group %0;" :: "n"(STAGES - 2) : "memory");
            __syncthreads();
            uint32_t stg = sb + (uint32_t)s * STGB;

            // issue next-stage loads first (overlap with MMA)
            if (c + STAGES - 1 < NCHUNK) {
                uint32_t ds = sb + (uint32_t)(((unsigned)(s + STAGES - 1)) & (STAGES - 1)) * STGB;
                cp16(ds + d0, p0); cp16(ds + d0 + 16, p0 + 8); p0 += GBK;
                cp16(ds + d1, p1);      cp16(ds + d1 + 16, p1 + 8);
                cp16(ds + d1 + 32, p1 + 16); cp16(ds + d1 + 48, p1 + 24);
                p1 += GBK;
            }
            CP_COMMIT();

            uint32_t sA = stg + arow;
            uint32_t sB = stg + brow;

            // fragment double-buffer over 4 k-slices (16 halves each = 32 B)
            uint32_t af[2][2][4], br[2][4][4];
            #pragma unroll
            for (int mt = 0; mt < 2; mt++)
                ldsm4(af[0][mt], sA + mt * (16 * ROWB));
            #pragma unroll
            for (int bt = 0; bt < 4; bt++)
                ldsm4(br[0][bt], sB + bt * (16 * ROWB));

            #pragma unroll
            for (int ks = 0; ks < 4; ks++) {
                int cur = ks & 1, nxt = cur ^ 1;
                if (ks < 3) {
                    #pragma unroll
                    for (int mt = 0; mt < 2; mt++)
                        ldsm4(af[nxt][mt], sA + mt * (16 * ROWB) + (ks + 1) * 32);
                    #pragma unroll
                    for (int bt = 0; bt < 4; bt++)
                        ldsm4(br[nxt][bt], sB + bt * (16 * ROWB) + (ks + 1) * 32);
                }
                #pragma unroll
                for (int mt = 0; mt < 2; mt++)
                    #pragma unroll
                    for (int bt = 0; bt < 4; bt++) {
                        mma16816(acc[mt][2 * bt],     af[cur][mt], br[cur][bt][0], br[cur][bt][2]);
                        mma16816(acc[mt][2 * bt + 1], af[cur][mt], br[cur][bt][1], br[cur][bt][3]);
                    }
            }
        }
    }

    // epilogue
    int rbase = bm + wm + (l >> 2);
    int cbase = bn + wn + 2 * (l & 3);
    #pragma unroll
    for (int mt = 0; mt < 2; mt++) {
        #pragma unroll
        for (int nt = 0; nt < 8; nt++) {
            int col = cbase + nt * 8;
            float bx = bias[col], by = bias[col + 1];
            int rr0 = rbase + mt * 16;
            int rr1 = rr0 + 8;
            float v0x = acc[mt][nt][0] + bx;
            float v0y = acc[mt][nt][1] + by;
            float v1x = acc[mt][nt][2] + bx;
            float v1y = acc[mt][nt][3] + by;
            if (OUT_HALF) {
                __half* C = (__half*)Cv;
                *(__half2*)(C + (size_t)rr0 * ldc + col) = __floats2half2_rn(v0x, v0y);
                *(__half2*)(C + (size_t)rr1 * ldc + col) = __floats2half2_rn(v1x, v1y);
            } else {
                float* C = (float*)Cv;
                float2 q0 = *(const float2*)(res + (size_t)rr0 * EMB + col);
                float2 q1 = *(const float2*)(res + (size_t)rr1 * EMB + col);
                float2 o0 = {v0x + q0.x, v0y + q0.y};
                float2 o1 = {v1x + q1.x, v1y + q1.y};
                *(float2*)(C + (size_t)rr0 * ldc + col) = o0;
                *(float2*)(C + (size_t)rr1 * ldc + col) = o1;
            }
        }
    }
}

// ---------------- sliding-window attention (fp16 QKV) -> fp16 output --------
__global__ void __launch_bounds__(512) attn_kernel(
    const __half* __restrict__ QKV,
    __half* __restrict__ O)
{
    int s = blockIdx.x;
    int b = blockIdx.y;
    int h = threadIdx.x >> 5;
    int lane = threadIdx.x & 31;
    int t = s * BSZ + b;

    const __half2* qp = (const __half2*)(QKV + (size_t)t * NQKV + h * DHD);
    float2 qv = __half22float2(qp[lane]);

    float sc[PFW];
    #pragma unroll
    for (int p = 0; p < PFW; p++) {
        int sp = s + p - (PFW - 1);
        if (sp < 0) sp += SLEN;
        const __half2* kp = (const __half2*)(QKV + (size_t)(sp * BSZ + b) * NQKV + EMB + h * DHD);
        float2 kv = __half22float2(kp[lane]);
        float d = qv.x * kv.x + qv.y * kv.y;
        #pragma unroll
        for (int o = 16; o > 0; o >>= 1) d += __shfl_xor_sync(0xffffffffu, d, o);
        sc[p] = d * 0.125f;
    }

    float mx = sc[0];
    #pragma unroll
    for (int p = 1; p < PFW; p++) mx = fmaxf(mx, sc[p]);
    float sum = 0.f;
    #pragma unroll
    for (int p = 0; p < PFW; p++) { sc[p] = __expf(sc[p] - mx); sum += sc[p]; }
    float inv = 1.0f / sum;

    float o0 = 0.f, o1 = 0.f;
    #pragma unroll
    for (int p = 0; p < PFW; p++) {
        int sp = s + p - (PFW - 1);
        if (sp < 0) sp += SLEN;
        const __half2* vp = (const __half2*)(QKV + (size_t)(sp * BSZ + b) * NQKV + 2 * EMB + h * DHD);
        float2 vv = __half22float2(vp[lane]);
        float wgt = sc[p] * inv;
        o0 += wgt * vv.x;
        o1 += wgt * vv.y;
    }
    __half2* op = (__half2*)(O + (size_t)t * EMB + h * DHD);
    op[lane] = __floats2half2_rn(o0, o1);
}

// ---------------- launch ----------------------------------------------------
extern "C" void kernel_launch(void* const* d_in, const int* in_sizes, int n_in,
                              void* d_out, int out_size)
{
    const float* x    = (const float*)d_in[0];
    const float* ln_g = (const float*)d_in[1];
    const float* ln_b = (const float*)d_in[2];
    const float* Wq   = (const float*)d_in[3];
    const float* bq   = (const float*)d_in[4];
    const float* Wk   = (const float*)d_in[5];
    const float* bk   = (const float*)d_in[6];
    const float* Wv   = (const float*)d_in[7];
    const float* bv   = (const float*)d_in[8];
    const float* Wo   = (const float*)d_in[9];
    const float* bo   = (const float*)d_in[10];
    float* out = (float*)d_out;

    __half *xn, *att, *wh, *qkv;
    float *bias;
    cudaGetSymbolAddress((void**)&xn,   g_xn);
    cudaGetSymbolAddress((void**)&att,  g_att);
    cudaGetSymbolAddress((void**)&wh,   g_wh);
    cudaGetSymbolAddress((void**)&qkv,  g_qkv);
    cudaGetSymbolAddress((void**)&bias, g_bias);

    cudaFuncSetAttribute(gemm_mma<1>, cudaFuncAttributeMaxDynamicSharedMemorySize, GEMM_SMEM);
    cudaFuncSetAttribute(gemm_mma<0>, cudaFuncAttributeMaxDynamicSharedMemorySize, GEMM_SMEM);

    wprep_kernel<<<dim3(32, 32, 4), 256>>>(Wq, Wk, Wv, Wo, wh);
    bias_cat_kernel<<<12, 256>>>(bq, bk, bv, bias);
    ln_kernel<<<MTOK, 256>>>(x, ln_g, ln_b, xn);

    // fused QKV: C[4096, 3072] fp16
    gemm_mma<1><<<dim3(NQKV / GBN, MTOK / GBM), GTHR, GEMM_SMEM>>>(
        xn, wh, bias, nullptr, qkv, NQKV);

    attn_kernel<<<dim3(SLEN, BSZ), 512>>>(qkv, att);

    // output projection + residual (fp32 out)
    gemm_mma<0><<<dim3(EMB / GBN, MTOK / GBM), GTHR, GEMM_SMEM>>>(
        att, wh + (size_t)3 * EMB * EMB, bo, x, out, EMB);
}

// round 9
// speedup vs baseline: 1.1397x; 1.1397x over previous
#include <cuda_runtime.h>
#include <cuda_fp16.h>
#include <cstdint>

#define SLEN 2048
#define BSZ  2
#define EMB  1024
#define NH   16
#define DHD  64
#define PFW  16
#define MTOK (SLEN*BSZ)
#define GBK  32              // K per chunk
#define NCHUNK (EMB/GBK)     // 32
#define GBM  128
#define GBN  256
#define STAGES 4
#define ROWB 80              // padded smem row bytes (64 data + 16 pad)
#define SROWS 384            // A 128 rows + B 256 rows
#define STGB (SROWS*ROWB)    // 30720
#define GEMM_SMEM (STAGES*STGB)  // 122880
#define GTHR 512
#define NQKV 3072

// ---------------- scratch (static device arrays; no allocation) -------------
__device__ __align__(16) __half g_xn [MTOK*EMB];        // LN out fp16
__device__ __align__(16) __half g_att[MTOK*EMB];        // attn out fp16
__device__ __align__(16) __half g_wh [4*EMB*EMB];       // Wq|Wk|Wv|Wo fp16, [N][K]
__device__ __align__(16) __half g_qkv[MTOK*NQKV];       // fused QKV output (fp16)
__device__ float g_bias[NQKV];

// ---------------- PTX helpers ------------------------------------------------
__device__ __forceinline__ uint32_t s2u(const void* p) {
    uint32_t a;
    asm("{ .reg .u64 t; cvta.to.shared.u64 t, %1; cvt.u32.u64 %0, t; }" : "=r"(a) : "l"(p));
    return a;
}
__device__ __forceinline__ void cp16(uint32_t dst, const void* src) {
    asm volatile("cp.async.cg.shared.global [%0], [%1], 16;" :: "r"(dst), "l"(src));
}
#define CP_COMMIT() asm volatile("cp.async.commit_group;" ::: "memory")

__device__ __forceinline__ void ldsm4(uint32_t* r, uint32_t addr) {
    asm volatile("ldmatrix.sync.aligned.m8n8.x4.shared.b16 {%0,%1,%2,%3}, [%4];"
        : "=r"(r[0]), "=r"(r[1]), "=r"(r[2]), "=r"(r[3]) : "r"(addr));
}
__device__ __forceinline__ void mma16816(float* d, const uint32_t* a,
                                         uint32_t b0, uint32_t b1) {
    asm volatile("mma.sync.aligned.m16n8k16.row.col.f32.f16.f16.f32 "
        "{%0,%1,%2,%3}, {%4,%5,%6,%7}, {%8,%9}, {%0,%1,%2,%3};"
        : "+f"(d[0]), "+f"(d[1]), "+f"(d[2]), "+f"(d[3])
        : "r"(a[0]), "r"(a[1]), "r"(a[2]), "r"(a[3]), "r"(b0), "r"(b1));
}

// ---------------- merged prep: wprep (blocks 0..4095) + LN (4096..8191)
//                  + bias concat (8192..8203), one launch --------------------
__global__ void __launch_bounds__(256) prep_kernel(
    const float* __restrict__ x,
    const float* __restrict__ gamma,
    const float* __restrict__ beta,
    const float* __restrict__ W0, const float* __restrict__ W1,
    const float* __restrict__ W2, const float* __restrict__ W3,
    const float* __restrict__ bq, const float* __restrict__ bk,
    const float* __restrict__ bv,
    __half* __restrict__ Bh,
    __half* __restrict__ xn,
    float* __restrict__ bqkv)
{
    int bid = blockIdx.x;
    int tid = threadIdx.x;

    if (bid < 4096) {
        // ---- weight transpose + fp16 convert: W[K,N] -> Wh[N,K] ----
        int wsel = bid >> 10;
        int t = bid & 1023;
        int n0 = (t & 31) * 32;
        int k0 = (t >> 5) * 32;
        const float* W = (wsel == 0) ? W0 : (wsel == 1) ? W1
                       : (wsel == 2) ? W2 : W3;
        __half* B = Bh + (size_t)wsel * EMB * EMB;
        __shared__ float tile[32][33];
        int tx = tid & 31;
        int ty = tid >> 5;
        #pragma unroll
        for (int r = ty; r < 32; r += 8)
            tile[r][tx] = W[(size_t)(k0 + r) * EMB + n0 + tx];
        __syncthreads();
        #pragma unroll
        for (int r = ty; r < 32; r += 8)
            B[(size_t)(n0 + r) * EMB + (k0 + tx)] = __float2half(tile[tx][r]);
    } else if (bid < 8192) {
        // ---- LayerNorm row -> fp16 ----
        int row = bid - 4096;
        const float4 xv = ((const float4*)(x + (size_t)row * EMB))[tid];
        float s  = xv.x + xv.y + xv.z + xv.w;
        float s2 = xv.x*xv.x + xv.y*xv.y + xv.z*xv.z + xv.w*xv.w;
        #pragma unroll
        for (int o = 16; o > 0; o >>= 1) {
            s  += __shfl_xor_sync(0xffffffffu, s,  o);
            s2 += __shfl_xor_sync(0xffffffffu, s2, o);
        }
        __shared__ float rs[8], rs2[8];
        __shared__ float mean_s, rstd_s;
        int w = tid >> 5, l = tid & 31;
        if (l == 0) { rs[w] = s; rs2[w] = s2; }
        __syncthreads();
        if (tid == 0) {
            float ts = 0.f, ts2 = 0.f;
            #pragma unroll
            for (int i = 0; i < 8; i++) { ts += rs[i]; ts2 += rs2[i]; }
            float mean = ts * (1.0f / EMB);
            float var  = ts2 * (1.0f / EMB) - mean * mean;
            mean_s = mean;
            rstd_s = rsqrtf(var + 1e-5f);
        }
        __syncthreads();
        float mean = mean_s, r = rstd_s;
        float4 gv = ((const float4*)gamma)[tid];
        float4 bv2 = ((const float4*)beta)[tid];
        __half h[4];
        h[0] = __float2half((xv.x - mean) * r * gv.x + bv2.x);
        h[1] = __float2half((xv.y - mean) * r * gv.y + bv2.y);
        h[2] = __float2half((xv.z - mean) * r * gv.z + bv2.z);
        h[3] = __float2half((xv.w - mean) * r * gv.w + bv2.w);
        *(uint2*)(xn + (size_t)row * EMB + tid * 4) = *(uint2*)h;
    } else {
        // ---- bias concat ----
        int i = (bid - 8192) * 256 + tid;
        if (i < NQKV)
            bqkv[i] = (i < EMB) ? bq[i] : (i < 2*EMB) ? bk[i - EMB] : bv[i - 2*EMB];
    }
}

// ---------------- HMMA fp16 GEMM: C = A @ B^T + bias (+res) ----------------
// A: [M, 1024] fp16.  B: [N, 1024] fp16 ([N][K]).
// CTA tile 128x256, 16 warps, warp tile 32x64, 4-stage cp.async.
template<int OUT_HALF>
__global__ void __launch_bounds__(GTHR, 1) gemm_mma(
    const __half* __restrict__ A,
    const __half* __restrict__ B,
    const float* __restrict__ bias,
    const float* __restrict__ res,
    void* __restrict__ Cv,
    int ldc)
{
    extern __shared__ char smem[];
    uint32_t sb = s2u(smem);
    int tid = threadIdx.x;
    int w = tid >> 5, l = tid & 31;
    int bm = blockIdx.y * GBM;
    int bn = blockIdx.x * GBN;
    int wm = (w & 3) * 32;
    int wn = (w >> 2) * 64;

    // hoisted load addressing: each thread owns 3 (row, 16B-chunk) slots
    int r0 = tid >> 2;           // 0..127
    int ch = tid & 3;
    const __half* p0 = A + (size_t)(bm + r0) * EMB + ch * 8;        // A row r0
    const __half* p1 = B + (size_t)(bn + r0) * EMB + ch * 8;        // B row r0
    const __half* p2 = B + (size_t)(bn + r0 + 128) * EMB + ch * 8;  // B row r0+128
    uint32_t d0 = (uint32_t)r0 * ROWB + ch * 16;
    uint32_t d1 = d0 + 128 * ROWB;
    uint32_t d2 = d0 + 256 * ROWB;

    float acc[2][8][4];
    #pragma unroll
    for (int i = 0; i < 2; i++)
        #pragma unroll
        for (int j = 0; j < 8; j++)
            #pragma unroll
            for (int t = 0; t < 4; t++) acc[i][j][t] = 0.f;

    // prologue: fill STAGES-1 stages
    #pragma unroll
    for (int c = 0; c < STAGES - 1; c++) {
        uint32_t stg = sb + c * STGB;
        cp16(stg + d0, p0); p0 += GBK;
        cp16(stg + d1, p1); p1 += GBK;
        cp16(stg + d2, p2); p2 += GBK;
        CP_COMMIT();
    }

    uint32_t arow = (uint32_t)(wm + (l & 15)) * ROWB + ((l >> 4) << 4);
    uint32_t brow = (uint32_t)(128 + wn + (l & 15)) * ROWB + ((l >> 4) << 4);

    for (int c0 = 0; c0 < NCHUNK; c0 += STAGES) {
        #pragma unroll
        for (int s = 0; s < STAGES; s++) {
            int c = c0 + s;
            asm volatile("cp.async.wait_group %0;" :: "n"(STAGES - 2) : "memory");
            __syncthreads();
            uint32_t stg = sb + (uint32_t)s * STGB;   // compile-time stage offset

            // issue next-stage loads first (overlap with MMA)
            if (c + STAGES - 1 < NCHUNK) {
                uint32_t ds = sb + (uint32_t)(((unsigned)(s + STAGES - 1)) & (STAGES - 1)) * STGB;
                cp16(ds + d0, p0); p0 += GBK;
                cp16(ds + d1, p1); p1 += GBK;
                cp16(ds + d2, p2); p2 += GBK;
            }
            CP_COMMIT();

            uint32_t sA = stg + arow;
            uint32_t sB = stg + brow;

            #pragma unroll
            for (int ks = 0; ks < 2; ks++) {
                uint32_t af[2][4], br[4][4];
                #pragma unroll
                for (int mt = 0; mt < 2; mt++)
                    ldsm4(af[mt], sA + mt * (16 * ROWB) + ks * 32);
                #pragma unroll
                for (int bt = 0; bt < 4; bt++)
                    ldsm4(br[bt], sB + bt * (16 * ROWB) + ks * 32);
                #pragma unroll
                for (int mt = 0; mt < 2; mt++)
                    #pragma unroll
                    for (int bt = 0; bt < 4; bt++) {
                        mma16816(acc[mt][2 * bt],     af[mt], br[bt][0], br[bt][2]);
                        mma16816(acc[mt][2 * bt + 1], af[mt], br[bt][1], br[bt][3]);
                    }
            }
        }
    }

    // epilogue
    int rbase = bm + wm + (l >> 2);
    int cbase = bn + wn + 2 * (l & 3);
    #pragma unroll
    for (int mt = 0; mt < 2; mt++) {
        #pragma unroll
        for (int nt = 0; nt < 8; nt++) {
            int col = cbase + nt * 8;
            float bx = bias[col], by = bias[col + 1];
            int rr0 = rbase + mt * 16;
            int rr1 = rr0 + 8;
            float v0x = acc[mt][nt][0] + bx;
            float v0y = acc[mt][nt][1] + by;
            float v1x = acc[mt][nt][2] + bx;
            float v1y = acc[mt][nt][3] + by;
            if (OUT_HALF) {
                __half* C = (__half*)Cv;
                *(__half2*)(C + (size_t)rr0 * ldc + col) = __floats2half2_rn(v0x, v0y);
                *(__half2*)(C + (size_t)rr1 * ldc + col) = __floats2half2_rn(v1x, v1y);
            } else {
                float* C = (float*)Cv;
                float2 q0 = *(const float2*)(res + (size_t)rr0 * EMB + col);
                float2 q1 = *(const float2*)(res + (size_t)rr1 * EMB + col);
                float2 o0 = {v0x + q0.x, v0y + q0.y};
                float2 o1 = {v1x + q1.x, v1y + q1.y};
                *(float2*)(C + (size_t)rr0 * ldc + col) = o0;
                *(float2*)(C + (size_t)rr1 * ldc + col) = o1;
            }
        }
    }
}

// ---------------- sliding-window attention (fp16 QKV) -> fp16 output --------
__global__ void __launch_bounds__(512) attn_kernel(
    const __half* __restrict__ QKV,
    __half* __restrict__ O)
{
    int s = blockIdx.x;
    int b = blockIdx.y;
    int h = threadIdx.x >> 5;
    int lane = threadIdx.x & 31;
    int t = s * BSZ + b;

    const __half2* qp = (const __half2*)(QKV + (size_t)t * NQKV + h * DHD);
    float2 qv = __half22float2(qp[lane]);

    float sc[PFW];
    #pragma unroll
    for (int p = 0; p < PFW; p++) {
        int sp = s + p - (PFW - 1);
        if (sp < 0) sp += SLEN;
        const __half2* kp = (const __half2*)(QKV + (size_t)(sp * BSZ + b) * NQKV + EMB + h * DHD);
        float2 kv = __half22float2(kp[lane]);
        float d = qv.x * kv.x + qv.y * kv.y;
        #pragma unroll
        for (int o = 16; o > 0; o >>= 1) d += __shfl_xor_sync(0xffffffffu, d, o);
        sc[p] = d * 0.125f;
    }

    float mx = sc[0];
    #pragma unroll
    for (int p = 1; p < PFW; p++) mx = fmaxf(mx, sc[p]);
    float sum = 0.f;
    #pragma unroll
    for (int p = 0; p < PFW; p++) { sc[p] = __expf(sc[p] - mx); sum += sc[p]; }
    float inv = 1.0f / sum;

    float o0 = 0.f, o1 = 0.f;
    #pragma unroll
    for (int p = 0; p < PFW; p++) {
        int sp = s + p - (PFW - 1);
        if (sp < 0) sp += SLEN;
        const __half2* vp = (const __half2*)(QKV + (size_t)(sp * BSZ + b) * NQKV + 2 * EMB + h * DHD);
        float2 vv = __half22float2(vp[lane]);
        float wgt = sc[p] * inv;
        o0 += wgt * vv.x;
        o1 += wgt * vv.y;
    }
    __half2* op = (__half2*)(O + (size_t)t * EMB + h * DHD);
    op[lane] = __floats2half2_rn(o0, o1);
}

// ---------------- launch ----------------------------------------------------
extern "C" void kernel_launch(void* const* d_in, const int* in_sizes, int n_in,
                              void* d_out, int out_size)
{
    const float* x    = (const float*)d_in[0];
    const float* ln_g = (const float*)d_in[1];
    const float* ln_b = (const float*)d_in[2];
    const float* Wq   = (const float*)d_in[3];
    const float* bq   = (const float*)d_in[4];
    const float* Wk   = (const float*)d_in[5];
    const float* bk   = (const float*)d_in[6];
    const float* Wv   = (const float*)d_in[7];
    const float* bv   = (const float*)d_in[8];
    const float* Wo   = (const float*)d_in[9];
    const float* bo   = (const float*)d_in[10];
    float* out = (float*)d_out;

    __half *xn, *att, *wh, *qkv;
    float *bias;
    cudaGetSymbolAddress((void**)&xn,   g_xn);
    cudaGetSymbolAddress((void**)&att,  g_att);
    cudaGetSymbolAddress((void**)&wh,   g_wh);
    cudaGetSymbolAddress((void**)&qkv,  g_qkv);
    cudaGetSymbolAddress((void**)&bias, g_bias);

    cudaFuncSetAttribute(gemm_mma<1>, cudaFuncAttributeMaxDynamicSharedMemorySize, GEMM_SMEM);
    cudaFuncSetAttribute(gemm_mma<0>, cudaFuncAttributeMaxDynamicSharedMemorySize, GEMM_SMEM);

    // one merged prep launch: weight transpose + LN + bias concat
    prep_kernel<<<8204, 256>>>(x, ln_g, ln_b, Wq, Wk, Wv, Wo,
                               bq, bk, bv, wh, xn, bias);

    // fused QKV: C[4096, 3072] fp16
    gemm_mma<1><<<dim3(NQKV / GBN, MTOK / GBM), GTHR, GEMM_SMEM>>>(
        xn, wh, bias, nullptr, qkv, NQKV);

    attn_kernel<<<dim3(SLEN, BSZ), 512>>>(qkv, att);

    // output projection + residual (fp32 out)
    gemm_mma<0><<<dim3(EMB / GBN, MTOK / GBM), GTHR, GEMM_SMEM>>>(
        att, wh + (size_t)3 * EMB * EMB, bo, x, out, EMB);
}